// round 2
// baseline (speedup 1.0000x reference)
#include <cuda_runtime.h>
#include <cstdint>

#define NB      64
#define DMODEL  2048
#define DSSM    4096
#define NHEADS  64
#define HEADDIM 64
#define DSTATE  128
#define DINPROJ 8512   // 2*4096 + 2*128 + 64

// ---------------- scratch (device globals; no allocation) ----------------
__device__ __align__(16) int   g_xq [NB*512];        // hidden quantized, packed int8x4 (b-major)
__device__            float    g_xs [NB];
__device__ __align__(16) int   g_wq1[DINPROJ*512];   // W_in quantized, FRAGMENT-PERMUTED
__device__            float    g_ws1[DINPROJ];
__device__ __align__(16) float g_zx [NB*DINPROJ];    // zxbcdt fp32
__device__ __align__(16) float g_xfq[NB*DSSM];       // fake-quanted x
__device__ __align__(16) float g_Bq [NB*DSTATE];
__device__ __align__(16) float g_Cq [NB*DSTATE];
__device__            float    g_dtv[NB*NHEADS];
__device__            float    g_scl[NB*NHEADS];
__device__            float    g_bcd[NB];
__device__ __align__(16) float g_yraw[NB*DSSM];
__device__ __align__(16) int   g_yq [NB*1024];       // y quantized, packed (b-major)
__device__            float    g_ys [NB];
__device__ __align__(16) int   g_wq2[DMODEL*1024];   // W_out quantized, FRAGMENT-PERMUTED
__device__            float    g_ws2[DMODEL];

// ---------------- helpers ----------------
__device__ __forceinline__ int pack4(float a, float b, float c, float d, float s) {
    int q0 = (int)rintf(a / s);
    int q1 = (int)rintf(b / s);
    int q2 = (int)rintf(c / s);
    int q3 = (int)rintf(d / s);
    return (q0 & 0xFF) | ((q1 & 0xFF) << 8) | ((q2 & 0xFF) << 16) | (q3 << 24);
}

__device__ __forceinline__ void mma_s8(int* c, int a0, int a1, int a2, int a3,
                                       int b0, int b1) {
    asm volatile(
        "mma.sync.aligned.m16n8k32.row.col.s32.s8.s8.s32 "
        "{%0,%1,%2,%3}, {%4,%5,%6,%7}, {%8,%9}, {%0,%1,%2,%3};\n"
        : "+r"(c[0]), "+r"(c[1]), "+r"(c[2]), "+r"(c[3])
        : "r"(a0), "r"(a1), "r"(a2), "r"(a3), "r"(b0), "r"(b1));
}

// ---------------- K0: quantize hidden states ----------------
__global__ void quant_x_kernel(const float* __restrict__ hs) {
    __shared__ float sh[256];
    int b = blockIdx.x, t = threadIdx.x;
    const float* row = hs + b * DMODEL;
    float m = 0.f;
    for (int i = t; i < DMODEL; i += 256) m = fmaxf(m, fabsf(row[i]));
    sh[t] = m; __syncthreads();
    for (int s = 128; s > 0; s >>= 1) { if (t < s) sh[t] = fmaxf(sh[t], sh[t + s]); __syncthreads(); }
    float sc = sh[0] / 127.0f;
    if (sc == 0.f) sc = 1.f;
    if (t == 0) g_xs[b] = sc;
    const float4* row4 = (const float4*)row;
    for (int k4 = t; k4 < 512; k4 += 256) {
        float4 v = row4[k4];
        g_xq[b * 512 + k4] = pack4(v.x, v.y, v.z, v.w, sc);
    }
}

// ---------------- W quantization -> fragment-permuted layout ----------------
// Output layout: per 16-row block rb, per 64-k tile kt (16 ints of k4):
//   int4 at [ (rb*KT + kt)*64 + half*32 + lane ]:
//     row = rb*16 + (lane>>2) + half*8
//     components (x,y,z,w) = packed k4 offsets c, c+4, c+8, c+12  (c = lane&3)
// This is exactly the mma.m16n8k32 A-fragment for two k-steps.
template<int K>
__global__ void __launch_bounds__(256)
quant_w_perm(const float* __restrict__ W, int4* __restrict__ Ap, float* __restrict__ ws) {
    const int KT = K / 64;
    __shared__ float sm[256];
    __shared__ float ssc[16];
    int t = threadIdx.x;
    int lane = t & 31, half = (t >> 5) & 1, ktb = t >> 6;   // ktb: 0..3
    int c = lane & 3, rl = (lane >> 2) + half * 8;          // local row 0..15
    int rowg = blockIdx.x * 16 + rl;
    const float4* Wr = (const float4*)(W + (size_t)rowg * K);

    float m = 0.f;
    for (int kt = ktb; kt < KT; kt += 4) {
        #pragma unroll
        for (int j = 0; j < 4; j++) {
            float4 v = Wr[kt * 16 + c + j * 4];
            m = fmaxf(m, fmaxf(fmaxf(fabsf(v.x), fabsf(v.y)), fmaxf(fabsf(v.z), fabsf(v.w))));
        }
    }
    sm[t] = m; __syncthreads();
    if (t < 16) {
        float mm = 0.f;
        #pragma unroll
        for (int cc = 0; cc < 4; cc++)
            #pragma unroll
            for (int kb = 0; kb < 4; kb++)
                mm = fmaxf(mm, sm[((t & 7) << 2) + cc + ((t >> 3) << 5) + (kb << 6)]);
        float s = mm / 127.0f;
        if (s == 0.f) s = 1.f;
        ssc[t] = s;
        ws[blockIdx.x * 16 + t] = s;
    }
    __syncthreads();
    float s = ssc[rl];
    int4* outb = Ap + (size_t)blockIdx.x * KT * 64;
    for (int kt = ktb; kt < KT; kt += 4) {
        int q[4];
        #pragma unroll
        for (int j = 0; j < 4; j++) {
            float4 v = Wr[kt * 16 + c + j * 4];
            q[j] = pack4(v.x, v.y, v.z, v.w, s);
        }
        outb[kt * 64 + half * 32 + lane] = make_int4(q[0], q[1], q[2], q[3]);
    }
}

// ---------------- IMMA GEMM: out[n*M + m] = isum * ws[m] * xs[n] ----------------
// Warp: 16 rows x (NT*8) batches, full K. NSPLIT warps share a 16-row block.
template<int M, int K4, int NT, int NSPLIT>
__global__ void __launch_bounds__(128)
gemm_imma(const int4* __restrict__ Ap, const float* __restrict__ ws,
          const int* __restrict__ xq, const float* __restrict__ xs,
          float* __restrict__ out) {
    const int KT = K4 / 16;
    int warp = threadIdx.x >> 5, lane = threadIdx.x & 31;
    int gw = blockIdx.x * 4 + warp;
    int rowblk = gw / NSPLIT;
    int nt0 = (gw % NSPLIT) * NT;
    int c = lane & 3, l4 = lane >> 2;

    int acc[NT][4];
    #pragma unroll
    for (int nt = 0; nt < NT; nt++)
        #pragma unroll
        for (int i = 0; i < 4; i++) acc[nt][i] = 0;

    const int4* Ab = Ap + (size_t)rowblk * KT * 64;
    #pragma unroll 2
    for (int kt = 0; kt < KT; kt++) {
        int4 A0 = __ldcs(Ab + kt * 64 + lane);
        int4 A1 = __ldcs(Ab + kt * 64 + 32 + lane);
        #pragma unroll
        for (int s = 0; s < 2; s++) {
            int a0 = s ? A0.z : A0.x, a2 = s ? A0.w : A0.y;
            int a1 = s ? A1.z : A1.x, a3 = s ? A1.w : A1.y;
            int kb = kt * 16 + s * 8 + c;
            #pragma unroll
            for (int nt = 0; nt < NT; nt++) {
                int col = (nt0 + nt) * 8 + l4;
                int b0 = xq[col * K4 + kb];
                int b1 = xq[col * K4 + kb + 4];
                mma_s8(acc[nt], a0, a1, a2, a3, b0, b1);
            }
        }
    }

    int r0 = rowblk * 16 + l4;
    float w0 = ws[r0], w1 = ws[r0 + 8];
    #pragma unroll
    for (int nt = 0; nt < NT; nt++) {
        int n0 = (nt0 + nt) * 8 + c * 2;
        float s0 = xs[n0], s1 = xs[n0 + 1];
        out[(size_t)n0 * M + r0]           = (float)acc[nt][0] * (w0 * s0);
        out[(size_t)(n0 + 1) * M + r0]     = (float)acc[nt][1] * (w0 * s1);
        out[(size_t)n0 * M + r0 + 8]       = (float)acc[nt][2] * (w1 * s0);
        out[(size_t)(n0 + 1) * M + r0 + 8] = (float)acc[nt][3] * (w1 * s1);
    }
}

// ---------------- K2: xBC fake-quant, B.C dot, dt/softplus/exp (smem-staged) --------
__global__ void __launch_bounds__(512)
k2_kernel(const float* __restrict__ dt_bias, const float* __restrict__ A_log) {
    __shared__ float sx[4352];
    __shared__ float red[512];
    __shared__ float s_scale;
    int b = blockIdx.x, t = threadIdx.x;
    const float* xbc = g_zx + b * DINPROJ + DSSM;
    float m = 0.f;
    for (int i = t; i < 4352; i += 512) { float v = xbc[i]; sx[i] = v; m = fmaxf(m, fabsf(v)); }
    red[t] = m; __syncthreads();
    for (int s = 256; s > 0; s >>= 1) { if (t < s) red[t] = fmaxf(red[t], red[t + s]); __syncthreads(); }
    if (t == 0) { float sc = red[0] / 127.0f; s_scale = (sc == 0.f) ? 1.f : sc; }
    __syncthreads();
    float sc = s_scale;
    for (int i = t; i < 4352; i += 512) {
        float fq = rintf(sx[i] / sc) * sc;
        sx[i] = fq;
        if (i < DSSM)               g_xfq[b * DSSM + i] = fq;
        else if (i < DSSM + DSTATE) g_Bq[b * DSTATE + (i - DSSM)] = fq;
        else                        g_Cq[b * DSTATE + (i - DSSM - DSTATE)] = fq;
    }
    __syncthreads();
    float p = 0.f;
    if (t < DSTATE) p = sx[DSSM + t] * sx[DSSM + DSTATE + t];
    red[t] = p; __syncthreads();
    for (int s = 256; s > 0; s >>= 1) { if (t < s) red[t] += red[t + s]; __syncthreads(); }
    if (t == 0) g_bcd[b] = red[0];

    if (t < NHEADS) {
        float dtr = g_zx[b * DINPROJ + (2 * DSSM + 2 * DSTATE) + t] + dt_bias[t];
        float dts;
        if (dtr < -2.0f)      dts = 0.0f;
        else if (dtr > 2.0f)  dts = dtr;
        else                  dts = 0.69314718055994531f + 0.5f * dtr
                                    + (dtr * dtr) / 8.0f + (dtr * dtr * dtr) / 48.0f;
        float A  = -expf(A_log[t]);
        float x  = fmaxf(dts * A, -10000.0f);
        float x2 = x * x, x3 = x2 * x, x4 = x3 * x, x5 = x4 * x;
        float e  = 1.0f + x + x2 / 2.0f + x3 / 6.0f + x4 / 24.0f + x5 / 120.0f;
        e = fminf(fmaxf(e, 0.0f), 1.0f);
        g_dtv[b * NHEADS + t] = dts;
        g_scl[b * NHEADS + t] = e;
    }
}

// ---------------- K3: state readout (HBM-bound; state read exactly once) ----------------
__global__ void state_kernel(const float* __restrict__ S) {
    int warp = threadIdx.x >> 5, lane = threadIdx.x & 31;
    int wg = blockIdx.x * (blockDim.x >> 5) + warp;  // 0..65535
    int pg = wg & 15;
    int h  = (wg >> 4) & 63;
    int b  = wg >> 10;

    float4 C4 = ((const float4*)(g_Cq + b * DSTATE))[lane];
    const float* Sb = S + (((size_t)b * NHEADS + h) * HEADDIM + pg * 4) * DSTATE;

    float p[4];
    #pragma unroll
    for (int i = 0; i < 4; i++) {
        float4 s4 = ((const float4*)(Sb + i * DSTATE))[lane];
        p[i] = s4.x * C4.x + s4.y * C4.y + s4.z * C4.z + s4.w * C4.w;
    }
    #pragma unroll
    for (int o = 16; o; o >>= 1) {
        #pragma unroll
        for (int i = 0; i < 4; i++) p[i] += __shfl_xor_sync(0xFFFFFFFFu, p[i], o);
    }
    if (lane < 4) {
        float sv = 0.f;
        #pragma unroll
        for (int i = 0; i < 4; i++) if (lane == i) sv = p[i];
        int   pp  = pg * 4 + lane;
        float sc  = g_scl[b * NHEADS + h];
        float dtv = g_dtv[b * NHEADS + h];
        float bcd = g_bcd[b];
        float xv  = g_xfq[b * DSSM + h * HEADDIM + pp];
        g_yraw[b * DSSM + h * HEADDIM + pp] = sc * sv + dtv * bcd * xv;
    }
}

// ---------------- K4: gated epilogue + double fake-quant -> int8 y (smem-staged) ------
__global__ void __launch_bounds__(512)
k4_kernel(const float* __restrict__ Dp) {
    __shared__ float red[512];
    __shared__ __align__(16) float shy[DSSM];
    __shared__ float s_s1, s_s2;
    int b = blockIdx.x, t = threadIdx.x;
    const float* yr = g_yraw + b * DSSM;

    float m = 0.f;
    for (int i = t; i < DSSM; i += 512) { float v = yr[i]; shy[i] = v; m = fmaxf(m, fabsf(v)); }
    red[t] = m; __syncthreads();
    for (int s = 256; s > 0; s >>= 1) { if (t < s) red[t] = fmaxf(red[t], red[t + s]); __syncthreads(); }
    if (t == 0) { float s1 = red[0] / 127.0f; s_s1 = (s1 == 0.f) ? 1.f : s1; }
    __syncthreads();
    float s1 = s_s1;

    float m2 = 0.f;
    for (int i = t; i < DSSM; i += 512) {
        float yq1 = rintf(shy[i] / s1) * s1;                   // fake_quant(y)
        float z   = g_zx[b * DINPROJ + i];
        float y2  = (yq1 + Dp[i] * g_xfq[b * DSSM + i]) * fmaxf(z, 0.f);
        shy[i] = y2;
        m2 = fmaxf(m2, fabsf(y2));
    }
    red[t] = m2; __syncthreads();
    for (int s = 256; s > 0; s >>= 1) { if (t < s) red[t] = fmaxf(red[t], red[t + s]); __syncthreads(); }
    if (t == 0) { float s2 = red[0] / 127.0f; s_s2 = (s2 == 0.f) ? 1.f : s2; }
    __syncthreads();
    float s2 = s_s2;
    if (t == 0) g_ys[b] = (127.0f * s2) / 127.0f;   // effective scale after 3rd fake_quant

    const float4* shy4 = (const float4*)shy;
    for (int k4 = t; k4 < 1024; k4 += 512) {
        float4 v = shy4[k4];
        g_yq[b * 1024 + k4] = pack4(v.x, v.y, v.z, v.w, s2);
    }
}

// ---------------- launch ----------------
extern "C" void kernel_launch(void* const* d_in, const int* in_sizes, int n_in,
                              void* d_out, int out_size) {
    (void)in_sizes; (void)n_in; (void)out_size;
    const float* hs   = (const float*)d_in[0];
    const float* ssm  = (const float*)d_in[1];
    const float* Win  = (const float*)d_in[2];
    const float* dtb  = (const float*)d_in[3];
    const float* Alog = (const float*)d_in[4];
    const float* Dp   = (const float*)d_in[5];
    const float* Wout = (const float*)d_in[6];
    float* out = (float*)d_out;

    void *p_xq, *p_xs, *p_wq1, *p_ws1, *p_zx, *p_yq, *p_ys, *p_wq2, *p_ws2;
    cudaGetSymbolAddress(&p_xq,  g_xq);
    cudaGetSymbolAddress(&p_xs,  g_xs);
    cudaGetSymbolAddress(&p_wq1, g_wq1);
    cudaGetSymbolAddress(&p_ws1, g_ws1);
    cudaGetSymbolAddress(&p_zx,  g_zx);
    cudaGetSymbolAddress(&p_yq,  g_yq);
    cudaGetSymbolAddress(&p_ys,  g_ys);
    cudaGetSymbolAddress(&p_wq2, g_wq2);
    cudaGetSymbolAddress(&p_ws2, g_ws2);

    quant_x_kernel<<<NB, 256>>>(hs);
    quant_w_perm<DMODEL><<<DINPROJ / 16, 256>>>(Win, (int4*)p_wq1, (float*)p_ws1);
    // GEMM1: M=8512, K=2048 (K4=512), warp = 16 rows x 64 batches -> 532 warps
    gemm_imma<DINPROJ, 512, 8, 1><<<DINPROJ / 64, 128>>>(
        (const int4*)p_wq1, (const float*)p_ws1,
        (const int*)p_xq, (const float*)p_xs, (float*)p_zx);
    k2_kernel<<<NB, 512>>>(dtb, Alog);
    state_kernel<<<(NB * NHEADS * 16) / 8, 256>>>(ssm);
    k4_kernel<<<NB, 512>>>(Dp);
    quant_w_perm<DSSM><<<DMODEL / 16, 256>>>(Wout, (int4*)p_wq2, (float*)p_ws2);
    // GEMM2: M=2048, K=4096 (K4=1024), warp = 16 rows x 32 batches -> 256 warps
    gemm_imma<DMODEL, 1024, 4, 2><<<DMODEL / 32, 128>>>(
        (const int4*)p_wq2, (const float*)p_ws2,
        (const int*)p_yq, (const float*)p_ys, out);
}

// round 3
// speedup vs baseline: 1.2170x; 1.2170x over previous
#include <cuda_runtime.h>
#include <cstdint>

#define NB      64
#define DMODEL  2048
#define DSSM    4096
#define NHEADS  64
#define HEADDIM 64
#define DSTATE  128
#define DINPROJ 8512   // 2*4096 + 2*128 + 64

// ---------------- scratch (device globals; no allocation) ----------------
__device__ __align__(16) int   g_xq [NB*512];        // hidden quantized, B-FRAGMENT-PERMUTED
__device__            float    g_xs [NB];
__device__ __align__(16) int   g_wq1[DINPROJ*512];   // W_in quantized, A-FRAGMENT-PERMUTED
__device__            float    g_ws1[DINPROJ];
__device__ __align__(16) float g_zx [NB*DINPROJ];    // zxbcdt fp32
__device__ __align__(16) float g_xfq[NB*DSSM];       // fake-quanted x
__device__ __align__(16) float g_Cq [NB*DSTATE];
__device__            float    g_dtv[NB*NHEADS];
__device__            float    g_scl[NB*NHEADS];
__device__            float    g_bcd[NB];
__device__ __align__(16) float g_yraw[NB*DSSM];
__device__ __align__(16) int   g_yq [NB*1024];       // y quantized, B-FRAGMENT-PERMUTED
__device__            float    g_ys [NB];
__device__ __align__(16) int   g_wq2[DMODEL*1024];   // W_out quantized, A-FRAGMENT-PERMUTED
__device__            float    g_ws2[DMODEL];
__device__            int      g_xbcmax[NB];         // per-batch max|xBC| (float-as-int)
__device__            int      g_ymax  [NB];         // per-batch max|y_raw|

// ---------------- helpers ----------------
__device__ __forceinline__ int pack4(float a, float b, float c, float d, float s) {
    int q0 = (int)rintf(a / s);
    int q1 = (int)rintf(b / s);
    int q2 = (int)rintf(c / s);
    int q3 = (int)rintf(d / s);
    return (q0 & 0xFF) | ((q1 & 0xFF) << 8) | ((q2 & 0xFF) << 16) | (q3 << 24);
}

__device__ __forceinline__ void mma_s8(int* c, int a0, int a1, int a2, int a3,
                                       int b0, int b1) {
    asm volatile(
        "mma.sync.aligned.m16n8k32.row.col.s32.s8.s8.s32 "
        "{%0,%1,%2,%3}, {%4,%5,%6,%7}, {%8,%9}, {%0,%1,%2,%3};\n"
        : "+r"(c[0]), "+r"(c[1]), "+r"(c[2]), "+r"(c[3])
        : "r"(a0), "r"(a1), "r"(a2), "r"(a3), "r"(b0), "r"(b1));
}

// B-fragment scatter address (int index) for value covering k[4*j4 .. 4*j4+3] of column b.
// Layout entry (kt, nt, lane) as int4: components = packed k4 {c, c+4, c+8, c+12}.
__device__ __forceinline__ int bfrag_idx(int b, int j4) {
    int kt = j4 >> 4, comp = (j4 >> 2) & 3, c = j4 & 3;
    int nt = b >> 3, lane = ((b & 7) << 2) + c;
    return ((kt * 8 + nt) * 32 + lane) * 4 + comp;
}

// ---------------- K0: quantize hidden states (+ reset atomics) ----------------
__global__ void quant_x_kernel(const float* __restrict__ hs) {
    __shared__ float sh[256];
    int b = blockIdx.x, t = threadIdx.x;
    if (b == 0 && t < NB) { g_xbcmax[t] = 0; g_ymax[t] = 0; }
    const float* row = hs + b * DMODEL;
    float m = 0.f;
    for (int i = t; i < DMODEL; i += 256) m = fmaxf(m, fabsf(row[i]));
    sh[t] = m; __syncthreads();
    for (int s = 128; s > 0; s >>= 1) { if (t < s) sh[t] = fmaxf(sh[t], sh[t + s]); __syncthreads(); }
    float sc = sh[0] / 127.0f;
    if (sc == 0.f) sc = 1.f;
    if (t == 0) g_xs[b] = sc;
    const float4* row4 = (const float4*)row;
    for (int j4 = t; j4 < 512; j4 += 256) {
        float4 v = row4[j4];
        g_xq[bfrag_idx(b, j4)] = pack4(v.x, v.y, v.z, v.w, sc);
    }
}

// ---------------- W quantization -> A-fragment-permuted layout ----------------
template<int K>
__global__ void __launch_bounds__(256)
quant_w_perm(const float* __restrict__ W, int4* __restrict__ Ap, float* __restrict__ ws) {
    const int KT = K / 64;
    __shared__ float sm[256];
    __shared__ float ssc[16];
    int t = threadIdx.x;
    int lane = t & 31, half = (t >> 5) & 1, ktb = t >> 6;   // ktb: 0..3
    int c = lane & 3, rl = (lane >> 2) + half * 8;          // local row 0..15
    int rowg = blockIdx.x * 16 + rl;
    const float4* Wr = (const float4*)(W + (size_t)rowg * K);

    float m = 0.f;
    for (int kt = ktb; kt < KT; kt += 4) {
        #pragma unroll
        for (int j = 0; j < 4; j++) {
            float4 v = Wr[kt * 16 + c + j * 4];
            m = fmaxf(m, fmaxf(fmaxf(fabsf(v.x), fabsf(v.y)), fmaxf(fabsf(v.z), fabsf(v.w))));
        }
    }
    sm[t] = m; __syncthreads();
    if (t < 16) {
        float mm = 0.f;
        #pragma unroll
        for (int cc = 0; cc < 4; cc++)
            #pragma unroll
            for (int kb = 0; kb < 4; kb++)
                mm = fmaxf(mm, sm[((t & 7) << 2) + cc + ((t >> 3) << 5) + (kb << 6)]);
        float s = mm / 127.0f;
        if (s == 0.f) s = 1.f;
        ssc[t] = s;
        ws[blockIdx.x * 16 + t] = s;
    }
    __syncthreads();
    float s = ssc[rl];
    int4* outb = Ap + (size_t)blockIdx.x * KT * 64;
    for (int kt = ktb; kt < KT; kt += 4) {
        int q[4];
        #pragma unroll
        for (int j = 0; j < 4; j++) {
            float4 v = Wr[kt * 16 + c + j * 4];
            q[j] = pack4(v.x, v.y, v.z, v.w, s);
        }
        outb[kt * 64 + half * 32 + lane] = make_int4(q[0], q[1], q[2], q[3]);
    }
}

// ---------------- IMMA GEMM, fully coalesced fragments ----------------
// Warp: 16 rows x (NT*8) batches, full K. NSPLIT warps share a 16-row block.
template<int M, int K4, int NT, int NSPLIT, bool DOMAX>
__global__ void __launch_bounds__(128)
gemm_imma(const int4* __restrict__ Ap, const float* __restrict__ ws,
          const int4* __restrict__ xp, const float* __restrict__ xs,
          float* __restrict__ out) {
    const int KT = K4 / 16;
    int warp = threadIdx.x >> 5, lane = threadIdx.x & 31;
    int gw = blockIdx.x * 4 + warp;
    int rowblk = gw / NSPLIT;
    int nt0 = (gw % NSPLIT) * NT;
    int c = lane & 3, l4 = lane >> 2;

    int acc[NT][4];
    #pragma unroll
    for (int nt = 0; nt < NT; nt++)
        #pragma unroll
        for (int i = 0; i < 4; i++) acc[nt][i] = 0;

    const int4* Ab = Ap + (size_t)rowblk * KT * 64;
    #pragma unroll 2
    for (int kt = 0; kt < KT; kt++) {
        int4 A0 = Ab[kt * 64 + lane];
        int4 A1 = Ab[kt * 64 + 32 + lane];
        int4 Bv[NT];
        #pragma unroll
        for (int nt = 0; nt < NT; nt++)
            Bv[nt] = __ldg(xp + (kt * 8 + nt0 + nt) * 32 + lane);
        #pragma unroll
        for (int nt = 0; nt < NT; nt++)
            mma_s8(acc[nt], A0.x, A1.x, A0.y, A1.y, Bv[nt].x, Bv[nt].y);
        #pragma unroll
        for (int nt = 0; nt < NT; nt++)
            mma_s8(acc[nt], A0.z, A1.z, A0.w, A1.w, Bv[nt].z, Bv[nt].w);
    }

    int r0 = rowblk * 16 + l4;
    float w0 = ws[r0], w1 = ws[r0 + 8];
    #pragma unroll
    for (int nt = 0; nt < NT; nt++) {
        int n0 = (nt0 + nt) * 8 + c * 2;
        float s0 = xs[n0], s1 = xs[n0 + 1];
        float v00 = (float)acc[nt][0] * (w0 * s0);
        float v01 = (float)acc[nt][1] * (w0 * s1);
        float v10 = (float)acc[nt][2] * (w1 * s0);
        float v11 = (float)acc[nt][3] * (w1 * s1);
        out[(size_t)n0 * M + r0]           = v00;
        out[(size_t)(n0 + 1) * M + r0]     = v01;
        out[(size_t)n0 * M + r0 + 8]       = v10;
        out[(size_t)(n0 + 1) * M + r0 + 8] = v11;
        if (DOMAX && rowblk >= 256 && rowblk < 528) {   // rows 4096..8447 = xBC slice
            float m0 = fmaxf(fabsf(v00), fabsf(v10));   // batch n0
            float m1 = fmaxf(fabsf(v01), fabsf(v11));   // batch n0+1
            #pragma unroll
            for (int o = 4; o <= 16; o <<= 1) {         // reduce over l4 lanes
                m0 = fmaxf(m0, __shfl_xor_sync(0xFFFFFFFFu, m0, o));
                m1 = fmaxf(m1, __shfl_xor_sync(0xFFFFFFFFu, m1, o));
            }
            if (l4 == 0) {
                atomicMax(&g_xbcmax[n0],     __float_as_int(m0));
                atomicMax(&g_xbcmax[n0 + 1], __float_as_int(m1));
            }
        }
    }
}

// ---------------- K2: xBC fake-quant (single pass), B.C dot, dt/softplus/exp --------
__global__ void __launch_bounds__(512)
k2_kernel(const float* __restrict__ dt_bias, const float* __restrict__ A_log) {
    __shared__ float sB[DSTATE], sC[DSTATE];
    __shared__ float red[512];
    int b = blockIdx.x, t = threadIdx.x;
    float sc = __int_as_float(g_xbcmax[b]) / 127.0f;
    if (sc == 0.f) sc = 1.f;
    const float* xbc = g_zx + b * DINPROJ + DSSM;
    for (int i = t; i < 4352; i += 512) {
        float fq = rintf(xbc[i] / sc) * sc;
        if (i < DSSM)               g_xfq[b * DSSM + i] = fq;
        else if (i < DSSM + DSTATE) sB[i - DSSM] = fq;
        else { sC[i - DSSM - DSTATE] = fq; g_Cq[b * DSTATE + (i - DSSM - DSTATE)] = fq; }
    }
    __syncthreads();
    float p = (t < DSTATE) ? sB[t] * sC[t] : 0.f;
    red[t] = p; __syncthreads();
    for (int s = 256; s > 0; s >>= 1) { if (t < s) red[t] += red[t + s]; __syncthreads(); }
    if (t == 0) g_bcd[b] = red[0];

    if (t < NHEADS) {
        float dtr = g_zx[b * DINPROJ + (2 * DSSM + 2 * DSTATE) + t] + dt_bias[t];
        float dts;
        if (dtr < -2.0f)      dts = 0.0f;
        else if (dtr > 2.0f)  dts = dtr;
        else                  dts = 0.69314718055994531f + 0.5f * dtr
                                    + (dtr * dtr) / 8.0f + (dtr * dtr * dtr) / 48.0f;
        float A  = -expf(A_log[t]);
        float x  = fmaxf(dts * A, -10000.0f);
        float x2 = x * x, x3 = x2 * x, x4 = x3 * x, x5 = x4 * x;
        float e  = 1.0f + x + x2 / 2.0f + x3 / 6.0f + x4 / 24.0f + x5 / 120.0f;
        e = fminf(fmaxf(e, 0.0f), 1.0f);
        g_dtv[b * NHEADS + t] = dts;
        g_scl[b * NHEADS + t] = e;
    }
}

// ---------------- K3: state readout + per-batch max|y_raw| ----------------
__global__ void state_kernel(const float* __restrict__ S) {
    __shared__ float sm[8];
    int warp = threadIdx.x >> 5, lane = threadIdx.x & 31;
    int wg = blockIdx.x * 8 + warp;  // 0..65535
    int pg = wg & 15;
    int h  = (wg >> 4) & 63;
    int b  = wg >> 10;               // constant within block (8 | 1024)

    float4 C4 = ((const float4*)(g_Cq + b * DSTATE))[lane];
    const float* Sb = S + (((size_t)b * NHEADS + h) * HEADDIM + pg * 4) * DSTATE;

    float p[4];
    #pragma unroll
    for (int i = 0; i < 4; i++) {
        float4 s4 = ((const float4*)(Sb + i * DSTATE))[lane];
        p[i] = s4.x * C4.x + s4.y * C4.y + s4.z * C4.z + s4.w * C4.w;
    }
    #pragma unroll
    for (int o = 16; o; o >>= 1) {
        #pragma unroll
        for (int i = 0; i < 4; i++) p[i] += __shfl_xor_sync(0xFFFFFFFFu, p[i], o);
    }
    float av = 0.f;
    if (lane < 4) {
        float sv = 0.f;
        #pragma unroll
        for (int i = 0; i < 4; i++) if (lane == i) sv = p[i];
        int   pp  = pg * 4 + lane;
        float sc  = g_scl[b * NHEADS + h];
        float dtv = g_dtv[b * NHEADS + h];
        float bcd = g_bcd[b];
        float xv  = g_xfq[b * DSSM + h * HEADDIM + pp];
        float v   = sc * sv + dtv * bcd * xv;
        g_yraw[b * DSSM + h * HEADDIM + pp] = v;
        av = fabsf(v);
    }
    #pragma unroll
    for (int o = 16; o; o >>= 1) av = fmaxf(av, __shfl_xor_sync(0xFFFFFFFFu, av, o));
    if (lane == 0) sm[warp] = av;
    __syncthreads();
    if (threadIdx.x == 0) {
        float m = sm[0];
        #pragma unroll
        for (int i = 1; i < 8; i++) m = fmaxf(m, sm[i]);
        atomicMax(&g_ymax[b], __float_as_int(m));
    }
}

// ---------------- K4: gated epilogue + double fake-quant -> B-fragment int8 y --------
__global__ void __launch_bounds__(512)
k4_kernel(const float* __restrict__ Dp) {
    __shared__ float red[512];
    __shared__ __align__(16) float shy[DSSM];
    __shared__ float s_s2;
    int b = blockIdx.x, t = threadIdx.x;
    float s1 = __int_as_float(g_ymax[b]) / 127.0f;
    if (s1 == 0.f) s1 = 1.f;
    const float* yr = g_yraw + b * DSSM;

    float m2 = 0.f;
    for (int i = t; i < DSSM; i += 512) {
        float yq1 = rintf(yr[i] / s1) * s1;                    // fake_quant(y)
        float z   = g_zx[b * DINPROJ + i];
        float y2  = (yq1 + Dp[i] * g_xfq[b * DSSM + i]) * fmaxf(z, 0.f);
        shy[i] = y2;
        m2 = fmaxf(m2, fabsf(y2));
    }
    red[t] = m2; __syncthreads();
    for (int s = 256; s > 0; s >>= 1) { if (t < s) red[t] = fmaxf(red[t], red[t + s]); __syncthreads(); }
    if (t == 0) { float s2 = red[0] / 127.0f; s_s2 = (s2 == 0.f) ? 1.f : s2; }
    __syncthreads();
    float s2 = s_s2;
    if (t == 0) g_ys[b] = s2;   // effective scale after 3rd fake_quant: (127*s2)/127

    const float4* shy4 = (const float4*)shy;
    for (int j4 = t; j4 < 1024; j4 += 512) {
        float4 v = shy4[j4];
        g_yq[bfrag_idx(b, j4)] = pack4(v.x, v.y, v.z, v.w, s2);
    }
}

// ---------------- launch ----------------
extern "C" void kernel_launch(void* const* d_in, const int* in_sizes, int n_in,
                              void* d_out, int out_size) {
    (void)in_sizes; (void)n_in; (void)out_size;
    const float* hs   = (const float*)d_in[0];
    const float* ssm  = (const float*)d_in[1];
    const float* Win  = (const float*)d_in[2];
    const float* dtb  = (const float*)d_in[3];
    const float* Alog = (const float*)d_in[4];
    const float* Dp   = (const float*)d_in[5];
    const float* Wout = (const float*)d_in[6];
    float* out = (float*)d_out;

    void *p_xq, *p_xs, *p_wq1, *p_ws1, *p_zx, *p_yq, *p_ys, *p_wq2, *p_ws2;
    cudaGetSymbolAddress(&p_xq,  g_xq);
    cudaGetSymbolAddress(&p_xs,  g_xs);
    cudaGetSymbolAddress(&p_wq1, g_wq1);
    cudaGetSymbolAddress(&p_ws1, g_ws1);
    cudaGetSymbolAddress(&p_zx,  g_zx);
    cudaGetSymbolAddress(&p_yq,  g_yq);
    cudaGetSymbolAddress(&p_ys,  g_ys);
    cudaGetSymbolAddress(&p_wq2, g_wq2);
    cudaGetSymbolAddress(&p_ws2, g_ws2);

    quant_x_kernel<<<NB, 256>>>(hs);
    quant_w_perm<DMODEL><<<DINPROJ / 16, 256>>>(Win, (int4*)p_wq1, (float*)p_ws1);
    // GEMM1: 532 rowblocks x NSPLIT=2 -> 1064 warps, 266 blocks
    gemm_imma<DINPROJ, 512, 4, 2, true><<<266, 128>>>(
        (const int4*)p_wq1, (const float*)p_ws1,
        (const int4*)p_xq, (const float*)p_xs, (float*)p_zx);
    k2_kernel<<<NB, 512>>>(dtb, Alog);
    state_kernel<<<(NB * NHEADS * 16) / 8, 256>>>(ssm);
    k4_kernel<<<NB, 512>>>(Dp);
    quant_w_perm<DSSM><<<DMODEL / 16, 256>>>(Wout, (int4*)p_wq2, (float*)p_ws2);
    // GEMM2: 128 rowblocks x NSPLIT=4 -> 512 warps, 128 blocks
    gemm_imma<DMODEL, 1024, 2, 4, false><<<128, 128>>>(
        (const int4*)p_wq2, (const float*)p_ws2,
        (const int4*)p_yq, (const float*)p_ys, out);
}

// round 5
// speedup vs baseline: 1.3183x; 1.0832x over previous
#include <cuda_runtime.h>
#include <cstdint>

#define NB      64
#define DMODEL  2048
#define DSSM    4096
#define NHEADS  64
#define HEADDIM 64
#define DSTATE  128
#define DINPROJ 8512   // 2*4096 + 2*128 + 64

// ---------------- scratch (device globals; no allocation) ----------------
__device__ __align__(16) int   g_xq [NB*512];        // hidden quantized, B-FRAGMENT-PERMUTED
__device__            float    g_xs [NB];
__device__ __align__(16) int   g_wq1[DINPROJ*512];   // W_in quantized, A-FRAGMENT-PERMUTED
__device__            float    g_ws1[DINPROJ];
__device__ __align__(16) float g_zx [NB*DINPROJ];    // zxbcdt fp32
__device__ __align__(16) float g_yraw[NB*DSSM];
__device__ __align__(16) int   g_yq [NB*1024];       // y quantized, B-FRAGMENT-PERMUTED
__device__            float    g_ys [NB];
__device__ __align__(16) int   g_wq2[DMODEL*1024];   // W_out quantized, A-FRAGMENT-PERMUTED
__device__            float    g_ws2[DMODEL];
__device__            int      g_xbcmax[NB];         // per-batch max|xBC| (float-as-int)
__device__            int      g_ymax  [NB];         // per-batch max|y_raw|

// ---------------- helpers ----------------
__device__ __forceinline__ int pack4(float a, float b, float c, float d, float s) {
    int q0 = (int)rintf(a / s);
    int q1 = (int)rintf(b / s);
    int q2 = (int)rintf(c / s);
    int q3 = (int)rintf(d / s);
    return (q0 & 0xFF) | ((q1 & 0xFF) << 8) | ((q2 & 0xFF) << 16) | (q3 << 24);
}

__device__ __forceinline__ void mma_s8(int* c, int a0, int a1, int a2, int a3,
                                       int b0, int b1) {
    asm volatile(
        "mma.sync.aligned.m16n8k32.row.col.s32.s8.s8.s32 "
        "{%0,%1,%2,%3}, {%4,%5,%6,%7}, {%8,%9}, {%0,%1,%2,%3};\n"
        : "+r"(c[0]), "+r"(c[1]), "+r"(c[2]), "+r"(c[3])
        : "r"(a0), "r"(a1), "r"(a2), "r"(a3), "r"(b0), "r"(b1));
}

// B-fragment scatter address (int index) for value covering k[4*j4 .. 4*j4+3] of column b.
__device__ __forceinline__ int bfrag_idx(int b, int j4) {
    int kt = j4 >> 4, comp = (j4 >> 2) & 3, c = j4 & 3;
    int nt = b >> 3, lane = ((b & 7) << 2) + c;
    return ((kt * 8 + nt) * 32 + lane) * 4 + comp;
}

// ---------------- K0: quantize hidden states (+ reset atomics) ----------------
__global__ void quant_x_kernel(const float* __restrict__ hs) {
    __shared__ float sh[256];
    int b = blockIdx.x, t = threadIdx.x;
    if (b == 0 && t < NB) { g_xbcmax[t] = 0; g_ymax[t] = 0; }
    const float* row = hs + b * DMODEL;
    float m = 0.f;
    for (int i = t; i < DMODEL; i += 256) m = fmaxf(m, fabsf(row[i]));
    sh[t] = m; __syncthreads();
    for (int s = 128; s > 0; s >>= 1) { if (t < s) sh[t] = fmaxf(sh[t], sh[t + s]); __syncthreads(); }
    float sc = sh[0] / 127.0f;
    if (sc == 0.f) sc = 1.f;
    if (t == 0) g_xs[b] = sc;
    const float4* row4 = (const float4*)row;
    for (int j4 = t; j4 < 512; j4 += 256) {
        float4 v = row4[j4];
        g_xq[bfrag_idx(b, j4)] = pack4(v.x, v.y, v.z, v.w, sc);
    }
}

// ---------------- W quantization -> A-fragment-permuted layout ----------------
template<int K>
__global__ void __launch_bounds__(256)
quant_w_perm(const float* __restrict__ W, int4* __restrict__ Ap, float* __restrict__ ws) {
    const int KT = K / 64;
    __shared__ float sm[256];
    __shared__ float ssc[16];
    int t = threadIdx.x;
    int lane = t & 31, half = (t >> 5) & 1, ktb = t >> 6;   // ktb: 0..3
    int c = lane & 3, rl = (lane >> 2) + half * 8;          // local row 0..15
    int rowg = blockIdx.x * 16 + rl;
    const float4* Wr = (const float4*)(W + (size_t)rowg * K);

    float m = 0.f;
    for (int kt = ktb; kt < KT; kt += 4) {
        #pragma unroll
        for (int j = 0; j < 4; j++) {
            float4 v = Wr[kt * 16 + c + j * 4];
            m = fmaxf(m, fmaxf(fmaxf(fabsf(v.x), fabsf(v.y)), fmaxf(fabsf(v.z), fabsf(v.w))));
        }
    }
    sm[t] = m; __syncthreads();
    if (t < 16) {
        float mm = 0.f;
        #pragma unroll
        for (int cc = 0; cc < 4; cc++)
            #pragma unroll
            for (int kb = 0; kb < 4; kb++)
                mm = fmaxf(mm, sm[((t & 7) << 2) + cc + ((t >> 3) << 5) + (kb << 6)]);
        float s = mm / 127.0f;
        if (s == 0.f) s = 1.f;
        ssc[t] = s;
        ws[blockIdx.x * 16 + t] = s;
    }
    __syncthreads();
    float s = ssc[rl];
    int4* outb = Ap + (size_t)blockIdx.x * KT * 64;
    for (int kt = ktb; kt < KT; kt += 4) {
        int q[4];
        #pragma unroll
        for (int j = 0; j < 4; j++) {
            float4 v = Wr[kt * 16 + c + j * 4];
            q[j] = pack4(v.x, v.y, v.z, v.w, s);
        }
        outb[kt * 64 + half * 32 + lane] = make_int4(q[0], q[1], q[2], q[3]);
    }
}

// ---------------- IMMA GEMM, fully coalesced fragments ----------------
// row0: global row offset for out/max bookkeeping. domax_lim: local rowblks < lim do atomics.
template<int M, int K4, int NT, int NSPLIT, bool DOMAX>
__global__ void __launch_bounds__(128)
gemm_imma(const int4* __restrict__ Ap, const float* __restrict__ ws,
          const int4* __restrict__ xp, const float* __restrict__ xs,
          float* __restrict__ out, int row0, int domax_lim) {
    const int KT = K4 / 16;
    int warp = threadIdx.x >> 5, lane = threadIdx.x & 31;
    int gw = blockIdx.x * 4 + warp;
    int rowblk = gw / NSPLIT;
    int nt0 = (gw % NSPLIT) * NT;
    int c = lane & 3, l4 = lane >> 2;

    int acc[NT][4];
    #pragma unroll
    for (int nt = 0; nt < NT; nt++)
        #pragma unroll
        for (int i = 0; i < 4; i++) acc[nt][i] = 0;

    const int4* Ab = Ap + (size_t)rowblk * KT * 64;
    #pragma unroll 2
    for (int kt = 0; kt < KT; kt++) {
        int4 A0 = Ab[kt * 64 + lane];
        int4 A1 = Ab[kt * 64 + 32 + lane];
        int4 Bv[NT];
        #pragma unroll
        for (int nt = 0; nt < NT; nt++)
            Bv[nt] = __ldg(xp + (kt * 8 + nt0 + nt) * 32 + lane);
        #pragma unroll
        for (int nt = 0; nt < NT; nt++)
            mma_s8(acc[nt], A0.x, A1.x, A0.y, A1.y, Bv[nt].x, Bv[nt].y);
        #pragma unroll
        for (int nt = 0; nt < NT; nt++)
            mma_s8(acc[nt], A0.z, A1.z, A0.w, A1.w, Bv[nt].z, Bv[nt].w);
    }

    int r0 = row0 + rowblk * 16 + l4;
    float w0 = ws[rowblk * 16 + l4], w1 = ws[rowblk * 16 + l4 + 8];
    #pragma unroll
    for (int nt = 0; nt < NT; nt++) {
        int n0 = (nt0 + nt) * 8 + c * 2;
        float s0 = xs[n0], s1 = xs[n0 + 1];
        float v00 = (float)acc[nt][0] * (w0 * s0);
        float v01 = (float)acc[nt][1] * (w0 * s1);
        float v10 = (float)acc[nt][2] * (w1 * s0);
        float v11 = (float)acc[nt][3] * (w1 * s1);
        out[(size_t)n0 * M + r0]           = v00;
        out[(size_t)(n0 + 1) * M + r0]     = v01;
        out[(size_t)n0 * M + r0 + 8]       = v10;
        out[(size_t)(n0 + 1) * M + r0 + 8] = v11;
        if (DOMAX && rowblk < domax_lim) {
            float m0 = fmaxf(fabsf(v00), fabsf(v10));   // batch n0
            float m1 = fmaxf(fabsf(v01), fabsf(v11));   // batch n0+1
            #pragma unroll
            for (int o = 4; o <= 16; o <<= 1) {         // reduce over l4 lanes
                m0 = fmaxf(m0, __shfl_xor_sync(0xFFFFFFFFu, m0, o));
                m1 = fmaxf(m1, __shfl_xor_sync(0xFFFFFFFFu, m1, o));
            }
            if (l4 == 0) {
                atomicMax(&g_xbcmax[n0],     __float_as_int(m0));
                atomicMax(&g_xbcmax[n0 + 1], __float_as_int(m1));
            }
        }
    }
}

// ---------------- K3: fused state readout + fake-quant + dt/exp + bcd ----------------
__global__ void __launch_bounds__(256)
state_kernel(const float* __restrict__ S, const float* __restrict__ dt_bias,
             const float* __restrict__ A_log) {
    __shared__ float smax[8];
    int warp = threadIdx.x >> 5, lane = threadIdx.x & 31;
    int wg = blockIdx.x * 8 + warp;  // 0..65535
    int pg = wg & 15;
    int h  = (wg >> 4) & 63;
    int b  = wg >> 10;               // constant within block

    const float* zb = g_zx + (size_t)b * DINPROJ;
    float sc = __int_as_float(g_xbcmax[b]) / 127.0f;
    if (sc == 0.f) sc = 1.f;

    float4 Cr = ((const float4*)(zb + 2 * DSSM + DSTATE))[lane];
    float4 C4 = make_float4(rintf(Cr.x / sc) * sc, rintf(Cr.y / sc) * sc,
                            rintf(Cr.z / sc) * sc, rintf(Cr.w / sc) * sc);

    const float* Sb = S + (((size_t)b * NHEADS + h) * HEADDIM + pg * 4) * DSTATE;
    float p[4];
    #pragma unroll
    for (int i = 0; i < 4; i++) {
        float4 s4 = ((const float4*)(Sb + i * DSTATE))[lane];
        p[i] = s4.x * C4.x + s4.y * C4.y + s4.z * C4.z + s4.w * C4.w;
    }
    float4 Br = ((const float4*)(zb + 2 * DSSM))[lane];
    float bc = (rintf(Br.x / sc) * sc) * C4.x + (rintf(Br.y / sc) * sc) * C4.y
             + (rintf(Br.z / sc) * sc) * C4.z + (rintf(Br.w / sc) * sc) * C4.w;
    #pragma unroll
    for (int o = 16; o; o >>= 1) {
        #pragma unroll
        for (int i = 0; i < 4; i++) p[i] += __shfl_xor_sync(0xFFFFFFFFu, p[i], o);
        bc += __shfl_xor_sync(0xFFFFFFFFu, bc, o);
    }
    float dtr = zb[2 * DSSM + 2 * DSTATE + h] + dt_bias[h];
    float dts;
    if (dtr < -2.0f)      dts = 0.0f;
    else if (dtr > 2.0f)  dts = dtr;
    else                  dts = 0.69314718055994531f + 0.5f * dtr
                                + (dtr * dtr) / 8.0f + (dtr * dtr * dtr) / 48.0f;
    float A  = -expf(A_log[h]);
    float xA = fmaxf(dts * A, -10000.0f);
    float x2 = xA * xA, x3 = x2 * xA, x4 = x3 * xA, x5 = x4 * xA;
    float e  = 1.0f + xA + x2 / 2.0f + x3 / 6.0f + x4 / 24.0f + x5 / 120.0f;
    e = fminf(fmaxf(e, 0.0f), 1.0f);

    float av = 0.f;
    if (lane < 4) {
        float sv = 0.f;
        #pragma unroll
        for (int i = 0; i < 4; i++) if (lane == i) sv = p[i];
        int   pp = pg * 4 + lane;
        float xv = zb[DSSM + h * HEADDIM + pp];
        xv = rintf(xv / sc) * sc;                       // fake-quanted x
        float v = e * sv + dts * bc * xv;
        g_yraw[b * DSSM + h * HEADDIM + pp] = v;
        av = fabsf(v);
    }
    #pragma unroll
    for (int o = 16; o; o >>= 1) av = fmaxf(av, __shfl_xor_sync(0xFFFFFFFFu, av, o));
    if (lane == 0) smax[warp] = av;
    __syncthreads();
    if (threadIdx.x == 0) {
        float m = smax[0];
        #pragma unroll
        for (int i = 1; i < 8; i++) m = fmaxf(m, smax[i]);
        atomicMax(&g_ymax[b], __float_as_int(m));
    }
}

// ---------------- K4: single-pass gated epilogue -> B-fragment int8 y ----------------
__global__ void __launch_bounds__(1024)
k4_kernel(const float* __restrict__ Dp) {
    __shared__ float red[32];
    __shared__ float s_s2;
    int b = blockIdx.x, t = threadIdx.x;
    int lane = t & 31;
    float s1 = __int_as_float(g_ymax[b]) / 127.0f;
    if (s1 == 0.f) s1 = 1.f;
    float sc = __int_as_float(g_xbcmax[b]) / 127.0f;
    if (sc == 0.f) sc = 1.f;

    const float4* yr4 = (const float4*)(g_yraw + b * DSSM);
    const float4* z4  = (const float4*)(g_zx + (size_t)b * DINPROJ);
    const float4* x4  = z4 + DSSM / 4;
    const float4* D4  = (const float4*)Dp;

    float4 yv = yr4[t], zv = z4[t], xv = x4[t], dv = D4[t];
    float4 y2;
    y2.x = (rintf(yv.x / s1) * s1 + dv.x * (rintf(xv.x / sc) * sc)) * fmaxf(zv.x, 0.f);
    y2.y = (rintf(yv.y / s1) * s1 + dv.y * (rintf(xv.y / sc) * sc)) * fmaxf(zv.y, 0.f);
    y2.z = (rintf(yv.z / s1) * s1 + dv.z * (rintf(xv.z / sc) * sc)) * fmaxf(zv.z, 0.f);
    y2.w = (rintf(yv.w / s1) * s1 + dv.w * (rintf(xv.w / sc) * sc)) * fmaxf(zv.w, 0.f);

    float m = fmaxf(fmaxf(fabsf(y2.x), fabsf(y2.y)), fmaxf(fabsf(y2.z), fabsf(y2.w)));
    #pragma unroll
    for (int o = 16; o; o >>= 1) m = fmaxf(m, __shfl_xor_sync(0xFFFFFFFFu, m, o));
    if (lane == 0) red[t >> 5] = m;
    __syncthreads();
    if (t < 32) {
        float mm = red[t];
        #pragma unroll
        for (int o = 16; o; o >>= 1) mm = fmaxf(mm, __shfl_xor_sync(0xFFFFFFFFu, mm, o));
        if (t == 0) { float s2 = mm / 127.0f; s_s2 = (s2 == 0.f) ? 1.f : s2; }
    }
    __syncthreads();
    float s2 = s_s2;
    if (t == 0) g_ys[b] = s2;   // 3rd fake_quant is idempotent at this grid

    g_yq[bfrag_idx(b, t)] = pack4(y2.x, y2.y, y2.z, y2.w, s2);
}

// ---------------- launch: forked-capture graph (statics: no per-call alloc) -------
extern "C" void kernel_launch(void* const* d_in, const int* in_sizes, int n_in,
                              void* d_out, int out_size) {
    (void)in_sizes; (void)n_in; (void)out_size;
    const float* hs   = (const float*)d_in[0];
    const float* ssm  = (const float*)d_in[1];
    const float* Win  = (const float*)d_in[2];
    const float* dtb  = (const float*)d_in[3];
    const float* Alog = (const float*)d_in[4];
    const float* Dp   = (const float*)d_in[5];
    const float* Wout = (const float*)d_in[6];
    float* out = (float*)d_out;

    void *p_xq, *p_xs, *p_wq1, *p_ws1, *p_zx, *p_yq, *p_ys, *p_wq2, *p_ws2;
    cudaGetSymbolAddress(&p_xq,  g_xq);
    cudaGetSymbolAddress(&p_xs,  g_xs);
    cudaGetSymbolAddress(&p_wq1, g_wq1);
    cudaGetSymbolAddress(&p_ws1, g_ws1);
    cudaGetSymbolAddress(&p_zx,  g_zx);
    cudaGetSymbolAddress(&p_yq,  g_yq);
    cudaGetSymbolAddress(&p_ys,  g_ys);
    cudaGetSymbolAddress(&p_wq2, g_wq2);
    cudaGetSymbolAddress(&p_ws2, g_ws2);

    // Streams/events created ONCE on the first (correctness, pre-capture) call and
    // reused during capture -> no allocation during capture, baseline stays intact.
    static cudaStream_t s1 = nullptr, s2 = nullptr;
    static cudaEvent_t ef, ex, e1a, e3, e2;
    if (!s1) {
        cudaStreamCreateWithFlags(&s1, cudaStreamNonBlocking);
        cudaStreamCreateWithFlags(&s2, cudaStreamNonBlocking);
        cudaEventCreateWithFlags(&ef,  cudaEventDisableTiming);
        cudaEventCreateWithFlags(&ex,  cudaEventDisableTiming);
        cudaEventCreateWithFlags(&e1a, cudaEventDisableTiming);
        cudaEventCreateWithFlags(&e3,  cudaEventDisableTiming);
        cudaEventCreateWithFlags(&e2,  cudaEventDisableTiming);
    }

    // Split points: W_in rows [4096, 8512) = xBC+dt slice (276 rowblocks of 16),
    //               W_in rows [0, 4096)    = z slice      (256 rowblocks).
    const int4*  wq1a = (const int4*)p_wq1 + (size_t)4096 * 128;   // 4096 rows * 512 int / 4
    const float* ws1a = (const float*)p_ws1 + 4096;

    cudaEventRecord(ef, 0);
    cudaStreamWaitEvent(s1, ef, 0);
    cudaStreamWaitEvent(s2, ef, 0);

    // branch s1: xBC-half of W_in first (unblocks gemm1a), then z-half, then gemm1b
    quant_w_perm<DMODEL><<<276, 256, 0, s1>>>(Win + (size_t)4096 * DMODEL,
                                              (int4*)wq1a, (float*)ws1a);
    cudaEventRecord(e1a, s1);
    quant_w_perm<DMODEL><<<256, 256, 0, s1>>>(Win, (int4*)p_wq1, (float*)p_ws1);

    // branch s2: W_out quant (fully off critical path)
    quant_w_perm<DSSM><<<DMODEL / 16, 256, 0, s2>>>(Wout, (int4*)p_wq2, (float*)p_ws2);
    cudaEventRecord(e2, s2);

    // main chain
    quant_x_kernel<<<NB, 256>>>(hs);
    cudaEventRecord(ex, 0);
    cudaStreamWaitEvent(0, e1a, 0);
    // gemm1a: xBC+dt rows, 276 rowblocks x NSPLIT=2 -> 138 blocks; atomics for local rowblk<272
    gemm_imma<DINPROJ, 512, 4, 2, true><<<138, 128>>>(
        wq1a, ws1a, (const int4*)p_xq, (const float*)p_xs, (float*)p_zx, 4096, 272);

    // branch s1 (continues): gemm1b for z rows, overlapped with state_kernel
    cudaStreamWaitEvent(s1, ex, 0);
    gemm_imma<DINPROJ, 512, 4, 2, false><<<128, 128, 0, s1>>>(
        (const int4*)p_wq1, (const float*)p_ws1,
        (const int4*)p_xq, (const float*)p_xs, (float*)p_zx, 0, 0);
    cudaEventRecord(e3, s1);

    state_kernel<<<(NB * NHEADS * 16) / 8, 256>>>(ssm, dtb, Alog);
    cudaStreamWaitEvent(0, e3, 0);
    k4_kernel<<<NB, 1024>>>(Dp);
    cudaStreamWaitEvent(0, e2, 0);
    gemm_imma<DMODEL, 1024, 2, 4, false><<<128, 128>>>(
        (const int4*)p_wq2, (const float*)p_ws2,
        (const int4*)p_yq, (const float*)p_ys, out, 0, 0);
}